// round 3
// baseline (speedup 1.0000x reference)
#include <cuda_runtime.h>

// Problem constants (fixed shapes per reference)
#define NPTS 65536
#define DIM  256
#define KCB  4096

// GEMM tiling
#define BM 128
#define BN 128
#define BK 16
#define TM 8            // rows per thread (as 4 packed pairs)
#define TN 8            // cols per thread
#define NTHREADS 256

#define AS_LD (BM + 4)       // 132 floats: 528B row (16B aligned), bank-shifted
#define BS_LD (2 * BN + 4)   // 260 floats: 1040B row (16B aligned), bank-shifted

typedef unsigned long long ull;

// Scratch (allocation-free rule: __device__ globals)
__device__ float g_xsq[NPTS];
__device__ float g_csq[KCB];

__device__ __forceinline__ void ffma2(ull& d, ull a, ull b) {
    // two independent fp32 RN FMAs — bitwise identical to scalar fmaf
    asm("fma.rn.f32x2 %0, %1, %2, %0;" : "+l"(d) : "l"(a), "l"(b));
}
__device__ __forceinline__ ull pack2(float lo, float hi) {
    ull r;
    asm("mov.b64 %0, {%1, %2};" : "=l"(r) : "f"(lo), "f"(hi));
    return r;
}
__device__ __forceinline__ float2 unpack2(ull v) {
    float2 r;
    asm("mov.b64 {%0, %1}, %2;" : "=f"(r.x), "=f"(r.y) : "l"(v));
    return r;
}

// ---------------------------------------------------------------------------
// Kernel 1: per-row squared norms for x and codebook. One warp per row.
// ---------------------------------------------------------------------------
__global__ void sqnorm_kernel(const float* __restrict__ x,
                              const float* __restrict__ cb) {
    int warp = (blockIdx.x * blockDim.x + threadIdx.x) >> 5;
    int lane = threadIdx.x & 31;
    const float* src;
    float* dst;
    if (warp < NPTS) {
        src = x + (size_t)warp * DIM;
        dst = g_xsq + warp;
    } else {
        int r = warp - NPTS;
        if (r >= KCB) return;
        src = cb + (size_t)r * DIM;
        dst = g_csq + r;
    }
    float s = 0.f;
#pragma unroll
    for (int i = 0; i < DIM / 32; i++) {
        float v = src[lane + i * 32];
        s = fmaf(v, v, s);
    }
#pragma unroll
    for (int o = 16; o > 0; o >>= 1)
        s += __shfl_xor_sync(0xFFFFFFFFu, s, o);
    if (lane == 0) *dst = s;
}

// ---------------------------------------------------------------------------
// Kernel 2: fused distance-GEMM (packed f32x2) + argmin + gather.
// A tile transposed [k][m]; B tile transposed AND duplicated: Bs2[k][2n] =
// Bs2[k][2n+1] = cb[n][k], so both FFMA2 operands are plain 64-bit smem loads.
// ---------------------------------------------------------------------------
__global__ __launch_bounds__(NTHREADS, 2)
void vq_argmin_kernel(const float* __restrict__ x,
                      const float* __restrict__ cb,
                      float* __restrict__ out) {
    __shared__ float As[BK][AS_LD];
    __shared__ float Bs2[BK][BS_LD];
    __shared__ float red_val[BM][16];
    __shared__ int   red_idx[BM][16];

    const int tid = threadIdx.x;
    const int tx = tid & 15;         // column-group (owns cols tx*8..+7)
    const int ty = tid >> 4;         // row-group    (owns rows ty*8..+7)
    const int rowbase = blockIdx.x * BM;

    float xsq_r[TM];
#pragma unroll
    for (int i = 0; i < TM; i++)
        xsq_r[i] = g_xsq[rowbase + ty * TM + i];

    float bestv[TM];
    int   besti[TM];
#pragma unroll
    for (int i = 0; i < TM; i++) { bestv[i] = 3.4e38f; besti[i] = 0; }

    for (int nb = 0; nb < KCB; nb += BN) {
        ull acc2[TM / 2][TN];        // row-pairs x cols
#pragma unroll
        for (int i = 0; i < TM / 2; i++)
#pragma unroll
            for (int j = 0; j < TN; j++) acc2[i][j] = 0ull;

        for (int kb = 0; kb < DIM; kb += BK) {
            // Stage tiles: 512 float4 per matrix, 2 per thread.
#pragma unroll
            for (int i = 0; i < 2; i++) {
                int idx = tid * 2 + i;          // 0..511
                int m  = idx >> 2;              // row within tile
                int k4 = (idx & 3) * 4;         // dim quad within BK
                float4 a = *(const float4*)(x  + (size_t)(rowbase + m) * DIM + kb + k4);
                As[k4 + 0][m] = a.x; As[k4 + 1][m] = a.y;
                As[k4 + 2][m] = a.z; As[k4 + 3][m] = a.w;
                float4 b = *(const float4*)(cb + (size_t)(nb + m) * DIM + kb + k4);
                *(ull*)&Bs2[k4 + 0][2 * m] = pack2(b.x, b.x);
                *(ull*)&Bs2[k4 + 1][2 * m] = pack2(b.y, b.y);
                *(ull*)&Bs2[k4 + 2][2 * m] = pack2(b.z, b.z);
                *(ull*)&Bs2[k4 + 3][2 * m] = pack2(b.w, b.w);
            }
            __syncthreads();

#pragma unroll
            for (int k = 0; k < BK; k++) {
                ulonglong2 a01 = *(const ulonglong2*)&As[k][ty * TM];
                ulonglong2 a23 = *(const ulonglong2*)&As[k][ty * TM + 4];
                ull a[TM / 2] = { a01.x, a01.y, a23.x, a23.y };
                ulonglong2 b01 = *(const ulonglong2*)&Bs2[k][tx * 16];
                ulonglong2 b23 = *(const ulonglong2*)&Bs2[k][tx * 16 + 4];
                ulonglong2 b45 = *(const ulonglong2*)&Bs2[k][tx * 16 + 8];
                ulonglong2 b67 = *(const ulonglong2*)&Bs2[k][tx * 16 + 12];
                ull b[TN] = { b01.x, b01.y, b23.x, b23.y,
                              b45.x, b45.y, b67.x, b67.y };
#pragma unroll
                for (int i = 0; i < TM / 2; i++)
#pragma unroll
                    for (int j = 0; j < TN; j++)
                        ffma2(acc2[i][j], a[i], b[j]);
            }
            __syncthreads();
        }

        // Epilogue: dist = (x^2 - 2*dot) + c^2, strict < keeps earliest index.
#pragma unroll
        for (int j = 0; j < TN; j++) {
            int n = nb + tx * TN + j;
            float cs = g_csq[n];
#pragma unroll
            for (int i = 0; i < TM / 2; i++) {
                float2 d2 = unpack2(acc2[i][j]);
                float s0 = fmaf(-2.f, d2.x, xsq_r[2 * i]) + cs;
                float s1 = fmaf(-2.f, d2.y, xsq_r[2 * i + 1]) + cs;
                if (s0 < bestv[2 * i])     { bestv[2 * i]     = s0; besti[2 * i]     = n; }
                if (s1 < bestv[2 * i + 1]) { bestv[2 * i + 1] = s1; besti[2 * i + 1] = n; }
            }
        }
    }

    // Cross-thread reduction: 16 column-group threads per row.
#pragma unroll
    for (int i = 0; i < TM; i++) {
        red_val[ty * TM + i][tx] = bestv[i];
        red_idx[ty * TM + i][tx] = besti[i];
    }
    __syncthreads();

    if (tid < BM) {
        float bv = red_val[tid][0];
        int   bi = red_idx[tid][0];
#pragma unroll
        for (int t = 1; t < 16; t++) {
            float v = red_val[tid][t];
            int   id = red_idx[tid][t];
            // smaller index wins ties (jnp.argmin returns first occurrence)
            if (v < bv || (v == bv && id < bi)) { bv = v; bi = id; }
        }
        red_idx[tid][0] = bi;
        out[(size_t)NPTS * DIM + rowbase + tid] = (float)bi;
    }
    __syncthreads();

    // Gather: 2 threads per row, 32 float4 each (256 floats per row).
    {
        int r = tid >> 1;
        int h = tid & 1;
        int idx = red_idx[r][0];
        const float4* src = (const float4*)(cb + (size_t)idx * DIM) + h * 32;
        float4* dst = (float4*)(out + (size_t)(rowbase + r) * DIM) + h * 32;
#pragma unroll
        for (int i = 0; i < 32; i++) dst[i] = src[i];
    }
}

// ---------------------------------------------------------------------------
extern "C" void kernel_launch(void* const* d_in, const int* in_sizes, int n_in,
                              void* d_out, int out_size) {
    const float* x  = (const float*)d_in[0];   // (65536, 256) f32
    const float* cb = (const float*)d_in[1];   // (4096, 256)  f32
    float* out = (float*)d_out;

    int warps = NPTS + KCB;
    int blocks = (warps * 32 + 255) / 256;
    sqnorm_kernel<<<blocks, 256>>>(x, cb);

    vq_argmin_kernel<<<NPTS / BM, NTHREADS>>>(x, cb, out);
}

// round 4
// speedup vs baseline: 3.2228x; 3.2228x over previous
#include <cuda_runtime.h>

// Problem constants (fixed shapes per reference)
#define NPTS 65536
#define DIM  256
#define KCB  4096

// Tiling
#define BM 128
#define BN 128
#define BK 32
#define NTHREADS 256

#define A_LD 260   // floats per A row: 1040B (16B aligned)
#define B_LD 34    // floats per B row: 136B (8B aligned, conflict-free banks)

#define SMEM_BYTES ((BM * A_LD + BM * B_LD) * 4)

typedef unsigned long long ull;

// Scratch (allocation-free rule: __device__ globals)
__device__ float g_xsq[NPTS];
__device__ float g_csq[KCB];

__device__ __forceinline__ void ffma2(ull& d, ull a, ull b) {
    // two independent fp32 RN FMAs — bitwise identical to scalar fmaf
    asm("fma.rn.f32x2 %0, %1, %2, %0;" : "+l"(d) : "l"(a), "l"(b));
}
__device__ __forceinline__ float2 unpack2(ull v) {
    float2 r;
    asm("mov.b64 {%0, %1}, %2;" : "=f"(r.x), "=f"(r.y) : "l"(v));
    return r;
}

// ---------------------------------------------------------------------------
// Kernel 1: per-row squared norms for x and codebook. One warp per row.
// ---------------------------------------------------------------------------
__global__ void sqnorm_kernel(const float* __restrict__ x,
                              const float* __restrict__ cb) {
    int warp = (blockIdx.x * blockDim.x + threadIdx.x) >> 5;
    int lane = threadIdx.x & 31;
    const float* src;
    float* dst;
    if (warp < NPTS) {
        src = x + (size_t)warp * DIM;
        dst = g_xsq + warp;
    } else {
        int r = warp - NPTS;
        if (r >= KCB) return;
        src = cb + (size_t)r * DIM;
        dst = g_csq + r;
    }
    float s = 0.f;
#pragma unroll
    for (int i = 0; i < DIM / 32; i++) {
        float v = src[lane + i * 32];
        s = fmaf(v, v, s);
    }
#pragma unroll
    for (int o = 16; o > 0; o >>= 1)
        s += __shfl_xor_sync(0xFFFFFFFFu, s, o);
    if (lane == 0) *dst = s;
}

// ---------------------------------------------------------------------------
// Kernel 2: fused distance-GEMM with K-paired FFMA2 + argmin + gather.
// A (x tile, 128x256) resident in smem for the whole CTA; B tiles (128x32)
// streamed with register prefetch. acc2[i][j] holds (even-k, odd-k) partial
// dots; one horizontal add at epilogue.
// Thread (tx,ty): rows ty*8+i (i<8), cols tx+16*j (j<8).
// ---------------------------------------------------------------------------
__global__ __launch_bounds__(NTHREADS, 1)
void vq_argmin_kernel(const float* __restrict__ x,
                      const float* __restrict__ cb,
                      float* __restrict__ out) {
    extern __shared__ float smem[];
    float* As = smem;                    // [128][A_LD]
    float* Bs = smem + BM * A_LD;        // [128][B_LD]
    float* red_val = Bs;                 // alias: used only after all compute
    int*   red_idx = (int*)(Bs + BM * 16);

    const int tid = threadIdx.x;
    const int tx = tid & 15;
    const int ty = tid >> 4;
    const int rowbase = blockIdx.x * BM;

    // Stage the full A tile (128 rows x 256 dims) once. 32 float4 per thread.
#pragma unroll
    for (int i = 0; i < 32; i++) {
        int v = tid + NTHREADS * i;          // 0..8191
        int r = v >> 6;                      // 64 float4 per row
        int c4 = (v & 63) << 2;
        *(float4*)(As + r * A_LD + c4) =
            *(const float4*)(x + (size_t)(rowbase + r) * DIM + c4);
    }

    float xsq_r[8];
#pragma unroll
    for (int i = 0; i < 8; i++) xsq_r[i] = g_xsq[rowbase + ty * 8 + i];

    float bestv[8];
    int   besti[8];
#pragma unroll
    for (int i = 0; i < 8; i++) { bestv[i] = 3.4e38f; besti[i] = 0; }

    float4 bp[4];
#define LOAD_B(nb_, kb_)                                                       \
    {                                                                          \
        _Pragma("unroll")                                                      \
        for (int i_ = 0; i_ < 4; i_++) {                                       \
            int v_ = tid + NTHREADS * i_;                                      \
            int r_ = v_ >> 3;                                                  \
            int c4_ = (v_ & 7) << 2;                                           \
            bp[i_] = *(const float4*)(cb + (size_t)((nb_) + r_) * DIM + (kb_) + c4_); \
        }                                                                      \
    }

    LOAD_B(0, 0);

    for (int nb = 0; nb < KCB; nb += BN) {
        ull acc2[8][8];
#pragma unroll
        for (int i = 0; i < 8; i++)
#pragma unroll
            for (int j = 0; j < 8; j++) acc2[i][j] = 0ull;

        for (int kb = 0; kb < DIM; kb += BK) {
            __syncthreads();               // previous stage's consumers done
            // Commit prefetched B tile (two float2 stores: rows are 8B-aligned)
#pragma unroll
            for (int i = 0; i < 4; i++) {
                int v = tid + NTHREADS * i;
                int r = v >> 3;
                int c4 = (v & 7) << 2;
                float* p = Bs + r * B_LD + c4;
                *(float2*)(p)     = make_float2(bp[i].x, bp[i].y);
                *(float2*)(p + 2) = make_float2(bp[i].z, bp[i].w);
            }
            __syncthreads();

            // Prefetch next B tile while computing this one
            int nkb = kb + BK, nnb = nb;
            if (nkb == DIM) { nkb = 0; nnb += BN; }
            if (nnb < KCB) LOAD_B(nnb, nkb);

#pragma unroll
            for (int kp = 0; kp < BK / 2; kp++) {
                ull a[8], b[8];
#pragma unroll
                for (int i = 0; i < 8; i++)   // broadcast: 2 addrs per warp
                    a[i] = *(const ull*)(As + (ty * 8 + i) * A_LD + kb + 2 * kp);
#pragma unroll
                for (int j = 0; j < 8; j++)   // banks 2*tx(+1): conflict-free
                    b[j] = *(const ull*)(Bs + (tx + 16 * j) * B_LD + 2 * kp);
#pragma unroll
                for (int i = 0; i < 8; i++)
#pragma unroll
                    for (int j = 0; j < 8; j++)
                        ffma2(acc2[i][j], a[i], b[j]);
            }
        }

        // Fold this codeword tile into the running argmin.
        // dist = (x^2 - 2*dot) + c^2; strict < keeps earliest index
        // (within thread, n = nb + tx + 16*j is strictly increasing).
#pragma unroll
        for (int j = 0; j < 8; j++) {
            int n = nb + tx + 16 * j;
            float cs = g_csq[n];
#pragma unroll
            for (int i = 0; i < 8; i++) {
                float2 d = unpack2(acc2[i][j]);
                float s = fmaf(-2.f, d.x + d.y, xsq_r[i]) + cs;
                if (s < bestv[i]) { bestv[i] = s; besti[i] = n; }
            }
        }
    }

    // Cross-thread reduction (16 column-group threads per row). red_* aliases
    // the B tile, which is dead after the last compute stage.
    __syncthreads();
#pragma unroll
    for (int i = 0; i < 8; i++) {
        red_val[(ty * 8 + i) * 16 + tx] = bestv[i];
        red_idx[(ty * 8 + i) * 16 + tx] = besti[i];
    }
    __syncthreads();

    if (tid < BM) {
        float bv = red_val[tid * 16];
        int   bi = red_idx[tid * 16];
#pragma unroll
        for (int t = 1; t < 16; t++) {
            float v = red_val[tid * 16 + t];
            int   id = red_idx[tid * 16 + t];
            // smaller index wins ties (jnp.argmin returns first occurrence)
            if (v < bv || (v == bv && id < bi)) { bv = v; bi = id; }
        }
        red_idx[tid * 16] = bi;
        out[(size_t)NPTS * DIM + rowbase + tid] = (float)bi;
    }
    __syncthreads();

    // Gather: 2 threads per row, 32 float4 each (256 floats per row).
    {
        int r = tid >> 1;
        int h = tid & 1;
        int idx = red_idx[r * 16];
        const float4* src = (const float4*)(cb + (size_t)idx * DIM) + h * 32;
        float4* dst = (float4*)(out + (size_t)(rowbase + r) * DIM) + h * 32;
#pragma unroll
        for (int i = 0; i < 32; i++) dst[i] = src[i];
    }
#undef LOAD_B
}

// ---------------------------------------------------------------------------
extern "C" void kernel_launch(void* const* d_in, const int* in_sizes, int n_in,
                              void* d_out, int out_size) {
    const float* x  = (const float*)d_in[0];   // (65536, 256) f32
    const float* cb = (const float*)d_in[1];   // (4096, 256)  f32
    float* out = (float*)d_out;

    int warps = NPTS + KCB;
    int blocks = (warps * 32 + 255) / 256;
    sqnorm_kernel<<<blocks, 256>>>(x, cb);

    cudaFuncSetAttribute(vq_argmin_kernel,
                         cudaFuncAttributeMaxDynamicSharedMemorySize, SMEM_BYTES);
    vq_argmin_kernel<<<NPTS / BM, NTHREADS, SMEM_BYTES>>>(x, cb, out);
}

// round 7
// speedup vs baseline: 6.7200x; 2.0851x over previous
#include <cuda_runtime.h>
#include <cuda_bf16.h>
#include <cstdint>

#define NPTS 65536
#define DIM  256
#define KCB  4096

#define BM     128
#define NGROUP 64                      // codewords per n-group
#define NGROUPS (KCB / NGROUP)         // 64
#define NCHUNK (2 * NGROUPS)           // 128 (Ch,Cl per group)
#define NTHREADS 256

// smem byte offsets (192 KB total)
#define A_H 0
#define A_L 65536
#define B_0 131072
#define B_1 163840
#define SMEM_TOTAL 196608

// ---------------- device scratch (allocation-free rule) ----------------
__device__ float g_xsq[NPTS];
__device__ float g_csq[KCB];
__device__ __nv_bfloat16 g_xh[(size_t)NPTS * DIM];
__device__ __nv_bfloat16 g_xl[(size_t)NPTS * DIM];
__device__ __nv_bfloat16 g_ch[(size_t)KCB * DIM];
__device__ __nv_bfloat16 g_cl[(size_t)KCB * DIM];
__device__ float g_cval[NPTS][16];
__device__ int   g_cand[NPTS][16];

// ---------------- helpers ----------------
__device__ __forceinline__ uint32_t smem_u32(const void* p) {
    uint32_t a;
    asm("{ .reg .u64 t; cvta.to.shared.u64 t, %1; cvt.u32.u64 %0, t; }"
        : "=r"(a) : "l"(p));
    return a;
}
// rows have 512B pitch (32 x 16B units); swizzle permutes units within each
// 128B block by row&7 -> conflict-free ldmatrix and stores.
__device__ __forceinline__ uint32_t swz_off(uint32_t r, uint32_t u) {
    return r * 512u + (((u) & ~7u) | (((u) ^ (r)) & 7u)) * 16u;
}

#define LDSM4(r0, r1, r2, r3, addr)                                             \
    asm volatile("ldmatrix.sync.aligned.m8n8.x4.shared.b16 {%0,%1,%2,%3}, [%4];" \
                 : "=r"(r0), "=r"(r1), "=r"(r2), "=r"(r3) : "r"(addr))

#define MMA16816(d, a0, a1, a2, a3, b0, b1)                                     \
    asm volatile("mma.sync.aligned.m16n8k16.row.col.f32.bf16.bf16.f32 "        \
                 "{%0,%1,%2,%3}, {%4,%5,%6,%7}, {%8,%9}, {%0,%1,%2,%3};"       \
                 : "+f"((d)[0]), "+f"((d)[1]), "+f"((d)[2]), "+f"((d)[3])       \
                 : "r"(a0), "r"(a1), "r"(a2), "r"(a3), "r"(b0), "r"(b1))

#define CP16(sdst, gsrc)                                                        \
    asm volatile("cp.async.cg.shared.global [%0], [%1], 16;"                    \
                 :: "r"(sdst), "l"(gsrc) : "memory")
#define CP_COMMIT() asm volatile("cp.async.commit_group;" ::: "memory")
#define CP_WAIT1()  asm volatile("cp.async.wait_group 1;" ::: "memory")
#define CP_WAIT0()  asm volatile("cp.async.wait_group 0;" ::: "memory")

// ---------------------------------------------------------------------------
// Prep 1: bf16 hi/lo split of x and codebook. 8 elems per thread.
// ---------------------------------------------------------------------------
__global__ void split_kernel(const float* __restrict__ x,
                             const float* __restrict__ cb) {
    size_t base = ((size_t)blockIdx.x * NTHREADS + threadIdx.x) * 8;
    const float* src;
    __nv_bfloat16 *dh, *dl;
    size_t off;
    if (base < (size_t)NPTS * DIM) {
        src = x; off = base; dh = g_xh; dl = g_xl;
    } else {
        src = cb; off = base - (size_t)NPTS * DIM; dh = g_ch; dl = g_cl;
    }
    float4 a = *(const float4*)(src + off);
    float4 b = *(const float4*)(src + off + 4);
    float f[8] = {a.x, a.y, a.z, a.w, b.x, b.y, b.z, b.w};
    __align__(16) __nv_bfloat16 h[8], l[8];
#pragma unroll
    for (int i = 0; i < 8; i++) {
        h[i] = __float2bfloat16(f[i]);
        l[i] = __float2bfloat16(f[i] - __bfloat162float(h[i]));
    }
    *(uint4*)(dh + off) = *(uint4*)h;
    *(uint4*)(dl + off) = *(uint4*)l;
}

// ---------------------------------------------------------------------------
// Prep 2: squared norms. One warp per row.
// ---------------------------------------------------------------------------
__global__ void sqnorm_kernel(const float* __restrict__ x,
                              const float* __restrict__ cb) {
    int warp = (blockIdx.x * blockDim.x + threadIdx.x) >> 5;
    int lane = threadIdx.x & 31;
    const float* src;
    float* dst;
    if (warp < NPTS) { src = x + (size_t)warp * DIM; dst = g_xsq + warp; }
    else {
        int r = warp - NPTS;
        if (r >= KCB) return;
        src = cb + (size_t)r * DIM; dst = g_csq + r;
    }
    float s = 0.f;
#pragma unroll
    for (int i = 0; i < DIM / 32; i++) {
        float v = src[lane + i * 32];
        s = fmaf(v, v, s);
    }
#pragma unroll
    for (int o = 16; o > 0; o >>= 1) s += __shfl_xor_sync(0xFFFFFFFFu, s, o);
    if (lane == 0) *dst = s;
}

// ---------------------------------------------------------------------------
// Main: warp-level bf16 mma.sync distance GEMM (3-term split) + top-2 pool.
// CTA = 128 x-rows; A (Xh,Xl) resident in smem; codebook streamed as 128
// chunks (Ch/Cl alternating, 64 codewords x 256 dims each) via cp.async
// double buffer. Warp (wm=wid&3, wn=wid>>2) owns a 32x32 tile of scores.
// ---------------------------------------------------------------------------
__global__ __launch_bounds__(NTHREADS, 1) void vq_mma_kernel() {
    extern __shared__ char smem[];
    const uint32_t sb = smem_u32(smem);

    const int tid = threadIdx.x;
    const int lane = tid & 31;
    const int wid = tid >> 5;
    const int wm = wid & 3;
    const int wn = wid >> 2;
    const int rowbase = blockIdx.x * BM;

    // ldmatrix lane->(row, k-unit) mappings
    const uint32_t ra = (lane & 7) + ((lane >> 3) & 1) * 8;   // A x4
    const uint32_t ua = (uint32_t)(lane >> 4);
    const uint32_t rb = (lane & 7) + (lane >> 4) * 8;         // B x4
    const uint32_t ub = (uint32_t)((lane >> 3) & 1);

    // Stage A (Xh, Xl): 128 rows x 32 units each
#pragma unroll
    for (int i = 0; i < 16; i++) {
        int flat = tid + NTHREADS * i;
        int r = flat >> 5, u = flat & 31;
        const uint4* sh = (const uint4*)(g_xh + (size_t)(rowbase + r) * DIM) + u;
        const uint4* sl = (const uint4*)(g_xl + (size_t)(rowbase + r) * DIM) + u;
        uint32_t so = swz_off(r, u);
        *(uint4*)(smem + A_H + so) = *sh;
        *(uint4*)(smem + A_L + so) = *sl;
    }

    // Prefetch chunks 0 and 1 (Ch buf0, Cl buf1 of group 0)
#pragma unroll
    for (int c = 0; c < 2; c++) {
        const __nv_bfloat16* src = (c & 1) ? g_cl : g_ch;
        uint32_t boff = (c & 1) ? B_1 : B_0;
#pragma unroll
        for (int i = 0; i < 8; i++) {
            int flat = tid + NTHREADS * i;
            int r = flat >> 5, u = flat & 31;
            CP16(sb + boff + swz_off(r, u),
                 (const char*)(src + (size_t)r * DIM) + u * 16);
        }
        CP_COMMIT();
    }

    float my_xsq[4];
#pragma unroll
    for (int t = 0; t < 2; t++)
#pragma unroll
        for (int s = 0; s < 2; s++)
            my_xsq[t * 2 + s] =
                g_xsq[rowbase + wm * 32 + t * 16 + (lane >> 2) + s * 8];

    float v1[4], v2[4];
    int i1[4], i2[4];
#pragma unroll
    for (int i = 0; i < 4; i++) {
        v1[i] = 3.4e38f; v2[i] = 3.4e38f; i1[i] = 0; i2[i] = 0;
    }

    float acc[2][4][4];

    for (int c = 0; c < NCHUNK; c++) {
        if (c == NCHUNK - 1) CP_WAIT0(); else CP_WAIT1();
        __syncthreads();

        const int type = c & 1;
        const int g = c >> 1;
        const uint32_t boff = type ? B_1 : B_0;

        if (type == 0) {
#pragma unroll
            for (int t = 0; t < 2; t++)
#pragma unroll
                for (int j = 0; j < 4; j++)
#pragma unroll
                    for (int e = 0; e < 4; e++) acc[t][j][e] = 0.f;
        }

        const int nseg = (type == 0) ? 2 : 1;
        for (int sg = 0; sg < nseg; sg++) {
            const uint32_t aoff = (type == 0 && sg == 1) ? A_L : A_H;
            const uint32_t ar0 = wm * 32 + ra;
            const uint32_t ar1 = wm * 32 + 16 + ra;
            const uint32_t br0 = wn * 32 + rb;
            const uint32_t br1 = wn * 32 + 16 + rb;
#pragma unroll
            for (int ks = 0; ks < 16; ks++) {
                uint32_t au = ks * 2 + ua;
                uint32_t bu = ks * 2 + ub;
                uint32_t a0, a1, a2, a3, a4, a5, a6, a7;
                uint32_t b0, b1, b2, b3, b4, b5, b6, b7;
                LDSM4(a0, a1, a2, a3, sb + aoff + swz_off(ar0, au));
                LDSM4(a4, a5, a6, a7, sb + aoff + swz_off(ar1, au));
                LDSM4(b0, b1, b2, b3, sb + boff + swz_off(br0, bu));
                LDSM4(b4, b5, b6, b7, sb + boff + swz_off(br1, bu));
                MMA16816(acc[0][0], a0, a1, a2, a3, b0, b1);
                MMA16816(acc[0][1], a0, a1, a2, a3, b2, b3);
                MMA16816(acc[0][2], a0, a1, a2, a3, b4, b5);
                MMA16816(acc[0][3], a0, a1, a2, a3, b6, b7);
                MMA16816(acc[1][0], a4, a5, a6, a7, b0, b1);
                MMA16816(acc[1][1], a4, a5, a6, a7, b2, b3);
                MMA16816(acc[1][2], a4, a5, a6, a7, b4, b5);
                MMA16816(acc[1][3], a4, a5, a6, a7, b6, b7);
            }
        }

        if (type == 1) {
            // Group g complete: fold scores into per-row top-2.
#pragma unroll
            for (int j = 0; j < 4; j++) {
                int col = g * NGROUP + wn * 32 + j * 8 + (lane & 3) * 2;
                float cs0 = __ldg(&g_csq[col]);
                float cs1 = __ldg(&g_csq[col + 1]);
#pragma unroll
                for (int t = 0; t < 2; t++)
#pragma unroll
                    for (int s = 0; s < 2; s++) {
                        int ri = t * 2 + s;
                        float s0 = fmaf(-2.f, acc[t][j][s * 2 + 0], my_xsq[ri]) + cs0;
                        float s1 = fmaf(-2.f, acc[t][j][s * 2 + 1], my_xsq[ri]) + cs1;
                        if (s0 < v1[ri]) { v2[ri] = v1[ri]; i2[ri] = i1[ri];
                                           v1[ri] = s0; i1[ri] = col; }
                        else if (s0 < v2[ri]) { v2[ri] = s0; i2[ri] = col; }
                        if (s1 < v1[ri]) { v2[ri] = v1[ri]; i2[ri] = i1[ri];
                                           v1[ri] = s1; i1[ri] = col + 1; }
                        else if (s1 < v2[ri]) { v2[ri] = s1; i2[ri] = col + 1; }
                    }
            }
        }

        __syncthreads();

        if (c + 2 < NCHUNK) {
            int nc = c + 2;
            const __nv_bfloat16* src = (nc & 1) ? g_cl : g_ch;
            uint32_t nboff = (nc & 1) ? B_1 : B_0;
            int ng = nc >> 1;
#pragma unroll
            for (int i = 0; i < 8; i++) {
                int flat = tid + NTHREADS * i;
                int r = flat >> 5, u = flat & 31;
                CP16(sb + nboff + swz_off(r, u),
                     (const char*)(src + (size_t)(ng * NGROUP + r) * DIM) + u * 16);
            }
            CP_COMMIT();
        }
    }

    // Emit 16 candidates per row (8 threads x top-2).
#pragma unroll
    for (int t = 0; t < 2; t++)
#pragma unroll
        for (int s = 0; s < 2; s++) {
            int ri = t * 2 + s;
            int row = rowbase + wm * 32 + t * 16 + (lane >> 2) + s * 8;
            int slot = (wn * 4 + (lane & 3)) * 2;
            g_cval[row][slot] = v1[ri];  g_cand[row][slot] = i1[ri];
            g_cval[row][slot + 1] = v2[ri]; g_cand[row][slot + 1] = i2[ri];
        }
}

// ---------------------------------------------------------------------------
// Rescore: approx-top-4 of the 16 candidates, exact fp32 rescore, write
// index + gather. One warp per row.
// ---------------------------------------------------------------------------
__global__ void rescore_kernel(const float* __restrict__ x,
                               const float* __restrict__ cb,
                               float* __restrict__ out) {
    int row = (blockIdx.x * blockDim.x + threadIdx.x) >> 5;
    int lane = threadIdx.x & 31;
    if (row >= NPTS) return;

    float v = (lane < 16) ? g_cval[row][lane] : 3.4e38f;
    int ci = (lane < 16) ? g_cand[row][lane] : 0x7FFFFFFF;

    int cand[4];
#pragma unroll
    for (int r = 0; r < 4; r++) {
        float bv = v; int bi = ci;
#pragma unroll
        for (int o = 16; o > 0; o >>= 1) {
            float ov = __shfl_xor_sync(0xFFFFFFFFu, bv, o);
            int oi = __shfl_xor_sync(0xFFFFFFFFu, bi, o);
            if (ov < bv || (ov == bv && oi < bi)) { bv = ov; bi = oi; }
        }
        cand[r] = bi;
        if (ci == bi) v = 3.4e38f;    // indices are unique across slots
    }

    const float4* xp = (const float4*)(x + (size_t)row * DIM);
    float4 xa = xp[lane * 2], xb = xp[lane * 2 + 1];
    float xsq = g_xsq[row];

    float best = 3.4e38f;
    int bi = KCB;
#pragma unroll
    for (int j = 0; j < 4; j++) {
        int cidx = cand[j];
        const float4* cp = (const float4*)(cb + (size_t)cidx * DIM);
        float4 ca = cp[lane * 2], cbv = cp[lane * 2 + 1];
        float d = 0.f;
        d = fmaf(xa.x, ca.x, d);  d = fmaf(xa.y, ca.y, d);
        d = fmaf(xa.z, ca.z, d);  d = fmaf(xa.w, ca.w, d);
        d = fmaf(xb.x, cbv.x, d); d = fmaf(xb.y, cbv.y, d);
        d = fmaf(xb.z, cbv.z, d); d = fmaf(xb.w, cbv.w, d);
#pragma unroll
        for (int o = 16; o > 0; o >>= 1) d += __shfl_xor_sync(0xFFFFFFFFu, d, o);
        float s = fmaf(-2.f, d, xsq) + g_csq[cidx];
        if (s < best || (s == best && cidx < bi)) { best = s; bi = cidx; }
    }

    if (lane == 0) out[(size_t)NPTS * DIM + row] = (float)bi;
    const float4* cp = (const float4*)(cb + (size_t)bi * DIM);
    float4* dst = (float4*)(out + (size_t)row * DIM);
    dst[lane * 2]     = cp[lane * 2];
    dst[lane * 2 + 1] = cp[lane * 2 + 1];
}

// ---------------------------------------------------------------------------
extern "C" void kernel_launch(void* const* d_in, const int* in_sizes, int n_in,
                              void* d_out, int out_size) {
    const float* x  = (const float*)d_in[0];   // (65536, 256) f32
    const float* cb = (const float*)d_in[1];   // (4096, 256)  f32
    float* out = (float*)d_out;

    int split_blocks = ((NPTS + KCB) * DIM / 8) / NTHREADS;   // 8704
    split_kernel<<<split_blocks, NTHREADS>>>(x, cb);

    int warps = NPTS + KCB;
    sqnorm_kernel<<<(warps * 32 + 255) / 256, 256>>>(x, cb);

    cudaFuncSetAttribute(vq_mma_kernel,
                         cudaFuncAttributeMaxDynamicSharedMemorySize, SMEM_TOTAL);
    vq_mma_kernel<<<NPTS / BM, NTHREADS, SMEM_TOTAL>>>();

    rescore_kernel<<<NPTS / 8, NTHREADS>>>(x, cb, out);
}